// round 8
// baseline (speedup 1.0000x reference)
#include <cuda_runtime.h>
#include <cuda_bf16.h>
#include <cstdint>
#include <math.h>

#define NN    20000
#define EE    320000
#define ET    (EE + NN)
#define FIN   128
#define HID   128
#define HEADS 4
#define DBIG  (HEADS * HID)
#define BGR   64
#define SLOPE 0.2f

// ----------------------------------------------------------------------------
// Scratch (device globals)
// ----------------------------------------------------------------------------
__device__ float g_xlr[(size_t)NN * 1024];   // fused [xl | xr] output (natural order)
__device__ float g_h1[(size_t)NN * DBIG];    // K-permuted + tf32-rounded
__device__ float g_h2[(size_t)NN * DBIG];    // K-permuted + tf32-rounded
__device__ float g_h3[(size_t)NN * HID];     // natural
__device__ float g_xp[(size_t)NN * FIN];     // x, K-permuted + tf32-rounded
__device__ float g_wt[1024 * 512];           // fused transposed weights (K-permuted, tf32)
__device__ int   g_deg[NN];
__device__ int   g_off[NN + 1];
__device__ int   g_cursor[NN];
__device__ int   g_csr_src[ET];
__device__ float g_pool[BGR * HID];

// ----------------------------------------------------------------------------
// Helpers
// ----------------------------------------------------------------------------
__device__ __forceinline__ uint32_t f2tf32(float f) {
    uint32_t u;
    asm("cvt.rna.tf32.f32 %0, %1;" : "=r"(u) : "f"(f));
    return u;
}
__device__ __forceinline__ float f2tf32f(float f) { return __uint_as_float(f2tf32(f)); }
// K-permutation within each 8-group: [0,4,1,5,2,6,3,7]
__device__ __forceinline__ int kperm(int k) {
    return (k & ~7) | (((k & 3) << 1) | ((k >> 2) & 1));
}
__device__ __forceinline__ uint32_t smem_u32(const void* p) {
    uint32_t a;
    asm("{ .reg .u64 t; cvta.to.shared.u64 t, %1; cvt.u32.u64 %0, t; }" : "=r"(a) : "l"(p));
    return a;
}
__device__ __forceinline__ void cp_async16(uint32_t dst, const void* src) {
    asm volatile("cp.async.cg.shared.global [%0], [%1], 16;" :: "r"(dst), "l"(src) : "memory");
}
__device__ __forceinline__ void cp_commit() {
    asm volatile("cp.async.commit_group;" ::: "memory");
}
template <int N>
__device__ __forceinline__ void cp_wait() {
    asm volatile("cp.async.wait_group %0;" :: "n"(N) : "memory");
}

// ----------------------------------------------------------------------------
// CSR build
// ----------------------------------------------------------------------------
__global__ void zero_kernel() {
    int i = blockIdx.x * blockDim.x + threadIdx.x;
    if (i < NN) g_deg[i] = 0;
}
__global__ void hist_kernel(const int* __restrict__ edst) {
    int e = blockIdx.x * blockDim.x + threadIdx.x;
    if (e >= ET) return;
    int d = (e < EE) ? edst[e] : (e - EE);
    atomicAdd(&g_deg[d], 1);
}
__global__ void scan_kernel() {
    __shared__ int part[1024];
    int t = threadIdx.x;
    const int chunk = (NN + 1023) / 1024;
    int beg = t * chunk, end = beg + chunk;
    if (end > NN) end = NN;
    int s = 0;
    for (int i = beg; i < end; i++) s += g_deg[i];
    part[t] = s;
    __syncthreads();
    for (int o = 1; o < 1024; o <<= 1) {
        int v = (t >= o) ? part[t - o] : 0;
        __syncthreads();
        part[t] += v;
        __syncthreads();
    }
    int run = (t == 0) ? 0 : part[t - 1];
    for (int i = beg; i < end; i++) {
        g_off[i] = run; g_cursor[i] = run; run += g_deg[i];
    }
    if (t == 1023) g_off[NN] = part[1023];
}
__global__ void scatter_kernel(const int* __restrict__ esrc, const int* __restrict__ edst) {
    int e = blockIdx.x * blockDim.x + threadIdx.x;
    if (e >= ET) return;
    int s, d;
    if (e < EE) { s = esrc[e]; d = edst[e]; }
    else        { s = e - EE;  d = e - EE; }
    int pos = atomicAdd(&g_cursor[d], 1);
    g_csr_src[pos] = s;
}

// ----------------------------------------------------------------------------
// x pre-pass: permute K within 8-groups + round to tf32
// ----------------------------------------------------------------------------
__global__ void permute_x_kernel(const float* __restrict__ x, float* __restrict__ xp) {
    int idx = blockIdx.x * blockDim.x + threadIdx.x;
    if (idx >= NN * FIN) return;
    int row = idx >> 7, k = idx & 127;
    xp[(size_t)row * FIN + kperm(k)] = f2tf32f(x[idx]);
}

// ----------------------------------------------------------------------------
// Weight transpose: WT[m][kperm(k)] = tf32(W[k][m])
// ----------------------------------------------------------------------------
__global__ void transpose_kernel(const float* __restrict__ W, float* __restrict__ WT,
                                 int K, int M) {
    __shared__ float t[32][33];
    int m0 = blockIdx.x * 32, k0 = blockIdx.y * 32;
    int tx = threadIdx.x, ty = threadIdx.y;
#pragma unroll
    for (int i = 0; i < 32; i += 8)
        t[ty + i][tx] = W[(size_t)(k0 + ty + i) * M + m0 + tx];
    __syncthreads();
    int kp = kperm(k0 + tx);
#pragma unroll
    for (int i = 0; i < 32; i += 8)
        WT[(size_t)(m0 + ty + i) * K + kp] = f2tf32f(t[tx][ty + i]);
}

// ----------------------------------------------------------------------------
// tf32 mma.sync GEMM, cp.async double-buffered, fragment-major K layout.
// Block tile 128x256, warp tile 64x64 (8 warps, 2x4), BK=32.
// ----------------------------------------------------------------------------
#define SM_STRIDE 36
#define SMEM_A_TILE (128 * SM_STRIDE)
#define SMEM_B_TILE (256 * SM_STRIDE)
__global__ __launch_bounds__(256, 1)
void gemm_mma(const float* __restrict__ A, const float* __restrict__ BT,
              const float* __restrict__ bias_l, const float* __restrict__ bias_r,
              float* __restrict__ C, int Nrows, int K, int Mout, int Mhalf) {
    extern __shared__ float sm[];
    float* smA = sm;                       // [2][128][36]
    float* smB = sm + 2 * SMEM_A_TILE;     // [2][256][36]
    uint32_t uA = smem_u32(smA);
    uint32_t uB = smem_u32(smB);

    int tid = threadIdx.x;
    int lane = tid & 31, wid = tid >> 5;
    int wn = wid & 3;        // 0..3 -> N offset 64*wn
    int wm = wid >> 2;       // 0..1 -> M offset 64*wm
    int g = lane >> 2, t = lane & 3;
    int brow = blockIdx.x * 128;
    int bcol = blockIdx.y * 256;

    int cprow = tid >> 3, cpc4 = (tid & 7) * 4;

    float acc[4][8][4];
#pragma unroll
    for (int a = 0; a < 4; a++)
#pragma unroll
        for (int b = 0; b < 8; b++)
#pragma unroll
            for (int c = 0; c < 4; c++) acc[a][b][c] = 0.f;

    const int NT = K >> 5;

    auto load_tile = [&](int kt, int buf) {
        int k0 = kt << 5;
#pragma unroll
        for (int i = 0; i < 4; i++) {
            int row = cprow + i * 32;
            int gr = brow + row; if (gr >= Nrows) gr = Nrows - 1;
            cp_async16(uA + (uint32_t)(buf * SMEM_A_TILE + row * SM_STRIDE + cpc4) * 4,
                       A + (size_t)gr * K + k0 + cpc4);
        }
#pragma unroll
        for (int i = 0; i < 8; i++) {
            int row = cprow + i * 32;
            cp_async16(uB + (uint32_t)(buf * SMEM_B_TILE + row * SM_STRIDE + cpc4) * 4,
                       BT + (size_t)(bcol + row) * K + k0 + cpc4);
        }
    };

    load_tile(0, 0);
    cp_commit();

    for (int kt = 0; kt < NT; kt++) {
        int buf = kt & 1;
        if (kt + 1 < NT) {
            load_tile(kt + 1, (kt + 1) & 1);
            cp_commit();
            cp_wait<1>();
        } else {
            cp_wait<0>();
        }
        __syncthreads();

        const float* Ab = smA + buf * SMEM_A_TILE;
        const float* Bb = smB + buf * SMEM_B_TILE;
#pragma unroll
        for (int kk = 0; kk < 32; kk += 8) {
            uint32_t af[4][4], bf[8][2];
#pragma unroll
            for (int mt = 0; mt < 4; mt++) {
                int r = wm * 64 + mt * 16 + g;
                uint2 x0 = *(const uint2*)(Ab + r * SM_STRIDE + kk + 2 * t);
                uint2 x1 = *(const uint2*)(Ab + (r + 8) * SM_STRIDE + kk + 2 * t);
                af[mt][0] = x0.x;
                af[mt][1] = x1.x;
                af[mt][2] = x0.y;
                af[mt][3] = x1.y;
            }
#pragma unroll
            for (int nt = 0; nt < 8; nt++) {
                int n = wn * 64 + nt * 8 + g;
                uint2 b = *(const uint2*)(Bb + n * SM_STRIDE + kk + 2 * t);
                bf[nt][0] = b.x;
                bf[nt][1] = b.y;
            }
#pragma unroll
            for (int mt = 0; mt < 4; mt++)
#pragma unroll
                for (int nt = 0; nt < 8; nt++) {
                    asm volatile(
                        "mma.sync.aligned.m16n8k8.row.col.f32.tf32.tf32.f32 "
                        "{%0,%1,%2,%3}, {%4,%5,%6,%7}, {%8,%9}, {%0,%1,%2,%3};"
                        : "+f"(acc[mt][nt][0]), "+f"(acc[mt][nt][1]),
                          "+f"(acc[mt][nt][2]), "+f"(acc[mt][nt][3])
                        : "r"(af[mt][0]), "r"(af[mt][1]), "r"(af[mt][2]), "r"(af[mt][3]),
                          "r"(bf[nt][0]), "r"(bf[nt][1]));
                }
        }
        __syncthreads();
    }

#pragma unroll
    for (int mt = 0; mt < 4; mt++) {
        int r0 = brow + wm * 64 + mt * 16 + g;
#pragma unroll
        for (int nt = 0; nt < 8; nt++) {
            int c = bcol + wn * 64 + nt * 8 + 2 * t;
            float b0, b1;
            if (c < Mhalf) { b0 = bias_l[c]; b1 = bias_l[c + 1]; }
            else           { b0 = bias_r[c - Mhalf]; b1 = bias_r[c - Mhalf + 1]; }
            if (r0 < Nrows) {
                float2 v = make_float2(acc[mt][nt][0] + b0, acc[mt][nt][1] + b1);
                *(float2*)(C + (size_t)r0 * Mout + c) = v;
            }
            if (r0 + 8 < Nrows) {
                float2 v = make_float2(acc[mt][nt][2] + b0, acc[mt][nt][3] + b1);
                *(float2*)(C + (size_t)(r0 + 8) * Mout + c) = v;
            }
        }
    }
}

// ----------------------------------------------------------------------------
// Fused GATv2 attention (online softmax), 2-edge ILP: one warp per (node, head).
// ----------------------------------------------------------------------------
template <int H, bool PERM>
__global__ __launch_bounds__(256)
void gatv2_fused(const float* __restrict__ xlr,
                 const float* __restrict__ att, const float* __restrict__ bias,
                 float* __restrict__ out) {
    const int S = 2 * H * 128;
    const int D = H * 128;
    int wg = blockIdx.x * 8 + (threadIdx.x >> 5);
    int node = wg / H;
    int h = wg % H;
    if (node >= NN) return;
    int lane = threadIdx.x & 31;
    int cbase = h * 128 + lane * 4;

    float4 rv = *(const float4*)(xlr + (size_t)node * S + D + cbase);
    float4 av = *(const float4*)(att + cbase);
    int s = g_off[node], e = g_off[node + 1];

    float m = -1e30f, den = 0.f;
    float4 acc = make_float4(0.f, 0.f, 0.f, 0.f);

    int j = s;
    for (; j + 2 <= e; j += 2) {
        int s0 = g_csr_src[j], s1 = g_csr_src[j + 1];
        float4 x0 = *(const float4*)(xlr + (size_t)s0 * S + cbase);
        float4 x1 = *(const float4*)(xlr + (size_t)s1 * S + cbase);
        float t0, t1, p0 = 0.f, p1 = 0.f;
        t0 = x0.x + rv.x; t0 = t0 > 0.f ? t0 : SLOPE * t0; p0 += av.x * t0;
        t1 = x1.x + rv.x; t1 = t1 > 0.f ? t1 : SLOPE * t1; p1 += av.x * t1;
        t0 = x0.y + rv.y; t0 = t0 > 0.f ? t0 : SLOPE * t0; p0 += av.y * t0;
        t1 = x1.y + rv.y; t1 = t1 > 0.f ? t1 : SLOPE * t1; p1 += av.y * t1;
        t0 = x0.z + rv.z; t0 = t0 > 0.f ? t0 : SLOPE * t0; p0 += av.z * t0;
        t1 = x1.z + rv.z; t1 = t1 > 0.f ? t1 : SLOPE * t1; p1 += av.z * t1;
        t0 = x0.w + rv.w; t0 = t0 > 0.f ? t0 : SLOPE * t0; p0 += av.w * t0;
        t1 = x1.w + rv.w; t1 = t1 > 0.f ? t1 : SLOPE * t1; p1 += av.w * t1;
#pragma unroll
        for (int o = 16; o; o >>= 1) {
            p0 += __shfl_xor_sync(0xffffffffu, p0, o);
            p1 += __shfl_xor_sync(0xffffffffu, p1, o);
        }
        float mm = fmaxf(m, fmaxf(p0, p1));
        float sc = __expf(m - mm);
        m = mm;
        den *= sc; acc.x *= sc; acc.y *= sc; acc.z *= sc; acc.w *= sc;
        float w0 = __expf(p0 - m), w1 = __expf(p1 - m);
        den += w0 + w1;
        acc.x += w0 * x0.x + w1 * x1.x;
        acc.y += w0 * x0.y + w1 * x1.y;
        acc.z += w0 * x0.z + w1 * x1.z;
        acc.w += w0 * x0.w + w1 * x1.w;
    }
    if (j < e) {
        int s0 = g_csr_src[j];
        float4 x0 = *(const float4*)(xlr + (size_t)s0 * S + cbase);
        float t0, p0 = 0.f;
        t0 = x0.x + rv.x; t0 = t0 > 0.f ? t0 : SLOPE * t0; p0 += av.x * t0;
        t0 = x0.y + rv.y; t0 = t0 > 0.f ? t0 : SLOPE * t0; p0 += av.y * t0;
        t0 = x0.z + rv.z; t0 = t0 > 0.f ? t0 : SLOPE * t0; p0 += av.z * t0;
        t0 = x0.w + rv.w; t0 = t0 > 0.f ? t0 : SLOPE * t0; p0 += av.w * t0;
#pragma unroll
        for (int o = 16; o; o >>= 1) p0 += __shfl_xor_sync(0xffffffffu, p0, o);
        float mm = fmaxf(m, p0);
        float sc = __expf(m - mm);
        m = mm;
        den *= sc; acc.x *= sc; acc.y *= sc; acc.z *= sc; acc.w *= sc;
        float w0 = __expf(p0 - m);
        den += w0;
        acc.x += w0 * x0.x; acc.y += w0 * x0.y; acc.z += w0 * x0.z; acc.w += w0 * x0.w;
    }

    float inv = 1.f / den;
    float4 o4;
    float v;
    v = acc.x * inv + bias[cbase + 0]; o4.x = v > 0.f ? v : expm1f(v);
    v = acc.y * inv + bias[cbase + 1]; o4.y = v > 0.f ? v : expm1f(v);
    v = acc.z * inv + bias[cbase + 2]; o4.z = v > 0.f ? v : expm1f(v);
    v = acc.w * inv + bias[cbase + 3]; o4.w = v > 0.f ? v : expm1f(v);

    if (PERM) {
        float r0 = __shfl_xor_sync(0xffffffffu, o4.x, 1);
        float r1 = __shfl_xor_sync(0xffffffffu, o4.y, 1);
        float r2 = __shfl_xor_sync(0xffffffffu, o4.z, 1);
        float r3 = __shfl_xor_sync(0xffffffffu, o4.w, 1);
        float4 w4;
        if ((lane & 1) == 0) w4 = make_float4(o4.x, r0, o4.y, r1);
        else                 w4 = make_float4(r2, o4.z, r3, o4.w);
        w4.x = f2tf32f(w4.x); w4.y = f2tf32f(w4.y);
        w4.z = f2tf32f(w4.z); w4.w = f2tf32f(w4.w);
        *(float4*)(out + (size_t)node * D + cbase) = w4;
    } else {
        *(float4*)(out + (size_t)node * D + cbase) = o4;
    }
}

// ----------------------------------------------------------------------------
// Pooling (batch is sorted -> contiguous segments, no atomics) + MLP
// ----------------------------------------------------------------------------
__global__ void pool_kernel(const int* __restrict__ batch) {
    int g = blockIdx.x;
    int t = threadIdx.x;
    __shared__ int seg[2];
    if (t < 2) {
        int target = g + t;
        int lo = 0, hi = NN;
        while (lo < hi) {
            int mid = (lo + hi) >> 1;
            if (batch[mid] < target) lo = mid + 1; else hi = mid;
        }
        seg[t] = lo;
    }
    __syncthreads();
    int lo = seg[0], hi = seg[1];
    float sum = 0.f;
    for (int i = lo; i < hi; i++) sum += g_h3[(size_t)i * HID + t];
    float c = fmaxf((float)(hi - lo), 1.0f);
    g_pool[g * HID + t] = sum / c;
}
__global__ void mlp_kernel(const float* __restrict__ W1, const float* __restrict__ b1,
                           const float* __restrict__ W2, const float* __restrict__ b2,
                           float* __restrict__ out) {
    int g = blockIdx.x;
    int t = threadIdx.x;
    __shared__ float p[HID];
    __shared__ float hid[HID];
    __shared__ float red[HID];
    p[t] = g_pool[g * HID + t];
    __syncthreads();
    float a = 0.f;
    for (int k = 0; k < HID; k++) a += p[k] * W1[k * HID + t];
    hid[t] = fmaxf(a + b1[t], 0.f);
    __syncthreads();
    for (int o = 0; o < 2; o++) {
        red[t] = hid[t] * W2[t * 2 + o];
        __syncthreads();
        for (int stp = 64; stp; stp >>= 1) {
            if (t < stp) red[t] += red[t + stp];
            __syncthreads();
        }
        if (t == 0) out[g * 2 + o] = red[0] + b2[o];
        __syncthreads();
    }
}

// ----------------------------------------------------------------------------
// Launch
// ----------------------------------------------------------------------------
extern "C" void kernel_launch(void* const* d_in, const int* in_sizes, int n_in,
                              void* d_out, int out_size) {
    const float* x     = (const float*)d_in[0];
    const int*   esrc  = (const int*)d_in[1];
    const int*   edst  = (const int*)d_in[2];
    const int*   batch = (const int*)d_in[3];
    const float* Wl1 = (const float*)d_in[4];
    const float* Wr1 = (const float*)d_in[5];
    const float* bl1 = (const float*)d_in[6];
    const float* br1 = (const float*)d_in[7];
    const float* att1  = (const float*)d_in[8];
    const float* bias1 = (const float*)d_in[9];
    const float* Wl2 = (const float*)d_in[10];
    const float* Wr2 = (const float*)d_in[11];
    const float* bl2 = (const float*)d_in[12];
    const float* br2 = (const float*)d_in[13];
    const float* att2  = (const float*)d_in[14];
    const float* bias2 = (const float*)d_in[15];
    const float* Wl3 = (const float*)d_in[16];
    const float* Wr3 = (const float*)d_in[17];
    const float* bl3 = (const float*)d_in[18];
    const float* br3 = (const float*)d_in[19];
    const float* att3  = (const float*)d_in[20];
    const float* bias3 = (const float*)d_in[21];
    const float* Wm1 = (const float*)d_in[22];
    const float* bm1 = (const float*)d_in[23];
    const float* Wm2 = (const float*)d_in[24];
    const float* bm2 = (const float*)d_in[25];
    float* out = (float*)d_out;

    float *p_xlr, *p_h1, *p_h2, *p_h3, *p_xp, *p_wt;
    cudaGetSymbolAddress((void**)&p_xlr, g_xlr);
    cudaGetSymbolAddress((void**)&p_h1, g_h1);
    cudaGetSymbolAddress((void**)&p_h2, g_h2);
    cudaGetSymbolAddress((void**)&p_h3, g_h3);
    cudaGetSymbolAddress((void**)&p_xp, g_xp);
    cudaGetSymbolAddress((void**)&p_wt, g_wt);

    const int SMEM = 2 * (SMEM_A_TILE + SMEM_B_TILE) * 4;  // 110592 bytes
    cudaFuncSetAttribute(gemm_mma, cudaFuncAttributeMaxDynamicSharedMemorySize, SMEM);

    const int RT = (NN + 127) / 128;  // 157 row tiles
    dim3 tb(32, 8);

    // --- front: layer-1 GEMM path first (gemm_mma at stream position 4 for ncu) ---
    permute_x_kernel<<<(NN * FIN + 255) / 256, 256>>>(x, p_xp);                 // 1
    transpose_kernel<<<dim3(16, 4), tb>>>(Wl1, p_wt, 128, 512);                 // 2
    transpose_kernel<<<dim3(16, 4), tb>>>(Wr1, p_wt + 512 * 128, 128, 512);     // 3
    gemm_mma<<<dim3(RT, 4), 256, SMEM>>>(p_xp, p_wt, bl1, br1, p_xlr,           // 4
                                         NN, 128, 1024, 512);

    // --- CSR build (only needed before attention) ---
    zero_kernel<<<(NN + 255) / 256, 256>>>();
    hist_kernel<<<(ET + 255) / 256, 256>>>(edst);
    scan_kernel<<<1, 1024>>>();
    scatter_kernel<<<(ET + 255) / 256, 256>>>(esrc, edst);

    gatv2_fused<HEADS, true><<<(NN * HEADS + 7) / 8, 256>>>(p_xlr, att1, bias1, p_h1);

    // Layer 2
    transpose_kernel<<<dim3(16, 16), tb>>>(Wl2, p_wt, 512, 512);
    transpose_kernel<<<dim3(16, 16), tb>>>(Wr2, p_wt + 512 * 512, 512, 512);
    gemm_mma<<<dim3(RT, 4), 256, SMEM>>>(p_h1, p_wt, bl2, br2, p_xlr, NN, 512, 1024, 512);
    gatv2_fused<HEADS, true><<<(NN * HEADS + 7) / 8, 256>>>(p_xlr, att2, bias2, p_h2);

    // Layer 3
    transpose_kernel<<<dim3(4, 16), tb>>>(Wl3, p_wt, 512, 128);
    transpose_kernel<<<dim3(4, 16), tb>>>(Wr3, p_wt + 128 * 512, 512, 128);
    gemm_mma<<<dim3(RT, 1), 256, SMEM>>>(p_h2, p_wt, bl3, br3, p_xlr, NN, 512, 256, 128);
    gatv2_fused<1, false><<<(NN + 7) / 8, 256>>>(p_xlr, att3, bias3, p_h3);

    // Pool + MLP
    pool_kernel<<<BGR, HID>>>(batch);
    mlp_kernel<<<BGR, HID>>>(Wm1, bm1, Wm2, bm2, out);
}

// round 9
// speedup vs baseline: 1.1401x; 1.1401x over previous
#include <cuda_runtime.h>
#include <cuda_bf16.h>
#include <cstdint>
#include <math.h>

#define NN    20000
#define EE    320000
#define ET    (EE + NN)
#define FIN   128
#define HID   128
#define HEADS 4
#define DBIG  (HEADS * HID)
#define BGR   64
#define SLOPE 0.2f

// ----------------------------------------------------------------------------
// Scratch (device globals)
// ----------------------------------------------------------------------------
__device__ float g_xlr[(size_t)NN * 1024];   // fused [xl | xr] output (natural order)
__device__ float g_h1[(size_t)NN * DBIG];    // K16-permuted + tf32-rounded
__device__ float g_h2[(size_t)NN * DBIG];    // K16-permuted + tf32-rounded
__device__ float g_h3[(size_t)NN * HID];     // natural
__device__ float g_xp[(size_t)NN * FIN];     // x, K16-permuted + tf32-rounded
__device__ float g_wt[1024 * 512];           // fused transposed weights (K16-permuted, tf32)
__device__ int   g_deg[NN];
__device__ int   g_off[NN + 1];
__device__ int   g_cursor[NN];
__device__ int   g_csr_src[ET];
__device__ float g_pool[BGR * HID];

// ----------------------------------------------------------------------------
// Helpers
// ----------------------------------------------------------------------------
__device__ __forceinline__ uint32_t f2tf32(float f) {
    uint32_t u;
    asm("cvt.rna.tf32.f32 %0, %1;" : "=r"(u) : "f"(f));
    return u;
}
__device__ __forceinline__ float f2tf32f(float f) { return __uint_as_float(f2tf32(f)); }
// 16-group K permutation: pos(k) = 4*(k&3) + ((k>>2)&3)  (self-inverse 4x4 transpose)
__device__ __forceinline__ int kperm16(int k) {
    return (k & ~15) | (((k & 3) << 2) | ((k >> 2) & 3));
}
__device__ __forceinline__ uint32_t smem_u32(const void* p) {
    uint32_t a;
    asm("{ .reg .u64 t; cvta.to.shared.u64 t, %1; cvt.u32.u64 %0, t; }" : "=r"(a) : "l"(p));
    return a;
}
__device__ __forceinline__ void cp_async16(uint32_t dst, const void* src) {
    asm volatile("cp.async.cg.shared.global [%0], [%1], 16;" :: "r"(dst), "l"(src) : "memory");
}
__device__ __forceinline__ void cp_commit() {
    asm volatile("cp.async.commit_group;" ::: "memory");
}
template <int N>
__device__ __forceinline__ void cp_wait() {
    asm volatile("cp.async.wait_group %0;" :: "n"(N) : "memory");
}

// ----------------------------------------------------------------------------
// CSR build
// ----------------------------------------------------------------------------
__global__ void zero_kernel() {
    int i = blockIdx.x * blockDim.x + threadIdx.x;
    if (i < NN) g_deg[i] = 0;
}
__global__ void hist_kernel(const int* __restrict__ edst) {
    int e = blockIdx.x * blockDim.x + threadIdx.x;
    if (e >= ET) return;
    int d = (e < EE) ? edst[e] : (e - EE);
    atomicAdd(&g_deg[d], 1);
}
__global__ void scan_kernel() {
    __shared__ int part[1024];
    int t = threadIdx.x;
    const int chunk = (NN + 1023) / 1024;
    int beg = t * chunk, end = beg + chunk;
    if (end > NN) end = NN;
    int s = 0;
    for (int i = beg; i < end; i++) s += g_deg[i];
    part[t] = s;
    __syncthreads();
    for (int o = 1; o < 1024; o <<= 1) {
        int v = (t >= o) ? part[t - o] : 0;
        __syncthreads();
        part[t] += v;
        __syncthreads();
    }
    int run = (t == 0) ? 0 : part[t - 1];
    for (int i = beg; i < end; i++) {
        g_off[i] = run; g_cursor[i] = run; run += g_deg[i];
    }
    if (t == 1023) g_off[NN] = part[1023];
}
__global__ void scatter_kernel(const int* __restrict__ esrc, const int* __restrict__ edst) {
    int e = blockIdx.x * blockDim.x + threadIdx.x;
    if (e >= ET) return;
    int s, d;
    if (e < EE) { s = esrc[e]; d = edst[e]; }
    else        { s = e - EE;  d = e - EE; }
    int pos = atomicAdd(&g_cursor[d], 1);
    g_csr_src[pos] = s;
}

// ----------------------------------------------------------------------------
// x pre-pass: 16-group permute + round to tf32
// ----------------------------------------------------------------------------
__global__ void permute_x_kernel(const float* __restrict__ x, float* __restrict__ xp) {
    int idx = blockIdx.x * blockDim.x + threadIdx.x;
    if (idx >= NN * FIN) return;
    int row = idx >> 7, k = idx & 127;
    xp[(size_t)row * FIN + kperm16(k)] = f2tf32f(x[idx]);
}

// ----------------------------------------------------------------------------
// Weight transpose: WT[m][kperm16(k)] = tf32(W[k][m])
// ----------------------------------------------------------------------------
__global__ void transpose_kernel(const float* __restrict__ W, float* __restrict__ WT,
                                 int K, int M) {
    __shared__ float t[32][33];
    int m0 = blockIdx.x * 32, k0 = blockIdx.y * 32;
    int tx = threadIdx.x, ty = threadIdx.y;
#pragma unroll
    for (int i = 0; i < 32; i += 8)
        t[ty + i][tx] = W[(size_t)(k0 + ty + i) * M + m0 + tx];
    __syncthreads();
    int kp = kperm16(k0 + tx);
#pragma unroll
    for (int i = 0; i < 32; i += 8)
        WT[(size_t)(m0 + ty + i) * K + kp] = f2tf32f(t[tx][ty + i]);
}

// ----------------------------------------------------------------------------
// tf32 mma.sync GEMM. Block 128x128, warp tile 64x32, 8 warps, 2 CTAs/SM.
// Smem rows are exactly 128B (32 floats), chunk-XOR swizzled: logical 16B-chunk
// c of row r stored at chunk c ^ (4*(r&1)). One LDS.128 per row yields
// fragments for TWO kk-steps (k = t, t+4, t+8, t+12 via kperm16 layout).
// Conflict-free loads and stores by construction.
// ----------------------------------------------------------------------------
#define SMEM_A_TILE (128 * 32)
#define SMEM_B_TILE (128 * 32)
__global__ __launch_bounds__(256, 2)
void gemm_mma(const float* __restrict__ A, const float* __restrict__ BT,
              const float* __restrict__ bias_l, const float* __restrict__ bias_r,
              float* __restrict__ C, int Nrows, int K, int Mout, int Mhalf) {
    extern __shared__ float sm[];
    float* smA = sm;                       // [2][128][32]
    float* smB = sm + 2 * SMEM_A_TILE;     // [2][128][32]
    uint32_t uA = smem_u32(smA);
    uint32_t uB = smem_u32(smB);

    int tid = threadIdx.x;
    int lane = tid & 31, wid = tid >> 5;
    int wm = wid & 1;        // M offset 64*wm
    int wn = wid >> 1;       // N offset 32*wn
    int g = lane >> 2, t = lane & 3;
    int brow = blockIdx.x * 128;
    int bcol = blockIdx.y * 128;

    int cprow = tid >> 3;
    int cc = tid & 7;                       // logical chunk
    int pch = cc ^ (4 * (cprow & 1));       // physical chunk (row parity swizzle)

    float acc[4][4][4];
#pragma unroll
    for (int a = 0; a < 4; a++)
#pragma unroll
        for (int b = 0; b < 4; b++)
#pragma unroll
            for (int c = 0; c < 4; c++) acc[a][b][c] = 0.f;

    const int NT = K >> 5;

    auto load_tile = [&](int kt, int buf) {
        int k0 = kt << 5;
#pragma unroll
        for (int i = 0; i < 4; i++) {
            int row = cprow + i * 32;       // parity(row) == parity(cprow)
            int gr = brow + row; if (gr >= Nrows) gr = Nrows - 1;
            cp_async16(uA + (uint32_t)(buf * SMEM_A_TILE + row * 32 + 4 * pch) * 4,
                       A + (size_t)gr * K + k0 + cc * 4);
        }
#pragma unroll
        for (int i = 0; i < 4; i++) {
            int row = cprow + i * 32;
            cp_async16(uB + (uint32_t)(buf * SMEM_B_TILE + row * 32 + 4 * pch) * 4,
                       BT + (size_t)(bcol + row) * K + k0 + cc * 4);
        }
    };

    load_tile(0, 0);
    cp_commit();

    for (int kt = 0; kt < NT; kt++) {
        int buf = kt & 1;
        if (kt + 1 < NT) {
            load_tile(kt + 1, (kt + 1) & 1);
            cp_commit();
            cp_wait<1>();
        } else {
            cp_wait<0>();
        }
        __syncthreads();

        const float* Ab = smA + buf * SMEM_A_TILE;
        const float* Bb = smB + buf * SMEM_B_TILE;
#pragma unroll
        for (int kb = 0; kb < 2; kb++) {          // 16-k halves of the 32-k tile
            int chb = kb * 4 + t;                 // logical chunk for this half
            uint4 bfv[4];
#pragma unroll
            for (int nt = 0; nt < 4; nt++) {
                int n = wn * 32 + nt * 8 + g;
                bfv[nt] = *(const uint4*)(Bb + n * 32 + 4 * (chb ^ (4 * (n & 1))));
            }
#pragma unroll
            for (int mt = 0; mt < 4; mt++) {
                int r = wm * 64 + mt * 16 + g;
                int chA = chb ^ (4 * (r & 1));    // r and r+8 share parity
                uint4 lo = *(const uint4*)(Ab + r * 32 + 4 * chA);
                uint4 hi = *(const uint4*)(Ab + (r + 8) * 32 + 4 * chA);
#pragma unroll
                for (int nt = 0; nt < 4; nt++) {
                    asm volatile(
                        "mma.sync.aligned.m16n8k8.row.col.f32.tf32.tf32.f32 "
                        "{%0,%1,%2,%3}, {%4,%5,%6,%7}, {%8,%9}, {%0,%1,%2,%3};"
                        : "+f"(acc[mt][nt][0]), "+f"(acc[mt][nt][1]),
                          "+f"(acc[mt][nt][2]), "+f"(acc[mt][nt][3])
                        : "r"(lo.x), "r"(hi.x), "r"(lo.y), "r"(hi.y),
                          "r"(bfv[nt].x), "r"(bfv[nt].y));
                    asm volatile(
                        "mma.sync.aligned.m16n8k8.row.col.f32.tf32.tf32.f32 "
                        "{%0,%1,%2,%3}, {%4,%5,%6,%7}, {%8,%9}, {%0,%1,%2,%3};"
                        : "+f"(acc[mt][nt][0]), "+f"(acc[mt][nt][1]),
                          "+f"(acc[mt][nt][2]), "+f"(acc[mt][nt][3])
                        : "r"(lo.z), "r"(hi.z), "r"(lo.w), "r"(hi.w),
                          "r"(bfv[nt].z), "r"(bfv[nt].w));
                }
            }
        }
        __syncthreads();
    }

#pragma unroll
    for (int mt = 0; mt < 4; mt++) {
        int r0 = brow + wm * 64 + mt * 16 + g;
#pragma unroll
        for (int nt = 0; nt < 4; nt++) {
            int c = bcol + wn * 32 + nt * 8 + 2 * t;
            float b0, b1;
            if (c < Mhalf) { b0 = bias_l[c]; b1 = bias_l[c + 1]; }
            else           { b0 = bias_r[c - Mhalf]; b1 = bias_r[c - Mhalf + 1]; }
            if (r0 < Nrows) {
                float2 v = make_float2(acc[mt][nt][0] + b0, acc[mt][nt][1] + b1);
                *(float2*)(C + (size_t)r0 * Mout + c) = v;
            }
            if (r0 + 8 < Nrows) {
                float2 v = make_float2(acc[mt][nt][2] + b0, acc[mt][nt][3] + b1);
                *(float2*)(C + (size_t)(r0 + 8) * Mout + c) = v;
            }
        }
    }
}

// ----------------------------------------------------------------------------
// Fused GATv2 attention (online softmax), 2-edge ILP: one warp per (node, head).
// PERM: quad-transpose output into kperm16 order + tf32 round (for next GEMM).
// ----------------------------------------------------------------------------
template <int H, bool PERM>
__global__ __launch_bounds__(256)
void gatv2_fused(const float* __restrict__ xlr,
                 const float* __restrict__ att, const float* __restrict__ bias,
                 float* __restrict__ out) {
    const int S = 2 * H * 128;
    const int D = H * 128;
    int wg = blockIdx.x * 8 + (threadIdx.x >> 5);
    int node = wg / H;
    int h = wg % H;
    if (node >= NN) return;
    int lane = threadIdx.x & 31;
    int cbase = h * 128 + lane * 4;

    float4 rv = *(const float4*)(xlr + (size_t)node * S + D + cbase);
    float4 av = *(const float4*)(att + cbase);
    int s = g_off[node], e = g_off[node + 1];

    float m = -1e30f, den = 0.f;
    float4 acc = make_float4(0.f, 0.f, 0.f, 0.f);

    int j = s;
    for (; j + 2 <= e; j += 2) {
        int s0 = g_csr_src[j], s1 = g_csr_src[j + 1];
        float4 x0 = *(const float4*)(xlr + (size_t)s0 * S + cbase);
        float4 x1 = *(const float4*)(xlr + (size_t)s1 * S + cbase);
        float t0, t1, p0 = 0.f, p1 = 0.f;
        t0 = x0.x + rv.x; t0 = t0 > 0.f ? t0 : SLOPE * t0; p0 += av.x * t0;
        t1 = x1.x + rv.x; t1 = t1 > 0.f ? t1 : SLOPE * t1; p1 += av.x * t1;
        t0 = x0.y + rv.y; t0 = t0 > 0.f ? t0 : SLOPE * t0; p0 += av.y * t0;
        t1 = x1.y + rv.y; t1 = t1 > 0.f ? t1 : SLOPE * t1; p1 += av.y * t1;
        t0 = x0.z + rv.z; t0 = t0 > 0.f ? t0 : SLOPE * t0; p0 += av.z * t0;
        t1 = x1.z + rv.z; t1 = t1 > 0.f ? t1 : SLOPE * t1; p1 += av.z * t1;
        t0 = x0.w + rv.w; t0 = t0 > 0.f ? t0 : SLOPE * t0; p0 += av.w * t0;
        t1 = x1.w + rv.w; t1 = t1 > 0.f ? t1 : SLOPE * t1; p1 += av.w * t1;
#pragma unroll
        for (int o = 16; o; o >>= 1) {
            p0 += __shfl_xor_sync(0xffffffffu, p0, o);
            p1 += __shfl_xor_sync(0xffffffffu, p1, o);
        }
        float mm = fmaxf(m, fmaxf(p0, p1));
        float sc = __expf(m - mm);
        m = mm;
        den *= sc; acc.x *= sc; acc.y *= sc; acc.z *= sc; acc.w *= sc;
        float w0 = __expf(p0 - m), w1 = __expf(p1 - m);
        den += w0 + w1;
        acc.x += w0 * x0.x + w1 * x1.x;
        acc.y += w0 * x0.y + w1 * x1.y;
        acc.z += w0 * x0.z + w1 * x1.z;
        acc.w += w0 * x0.w + w1 * x1.w;
    }
    if (j < e) {
        int s0 = g_csr_src[j];
        float4 x0 = *(const float4*)(xlr + (size_t)s0 * S + cbase);
        float t0, p0 = 0.f;
        t0 = x0.x + rv.x; t0 = t0 > 0.f ? t0 : SLOPE * t0; p0 += av.x * t0;
        t0 = x0.y + rv.y; t0 = t0 > 0.f ? t0 : SLOPE * t0; p0 += av.y * t0;
        t0 = x0.z + rv.z; t0 = t0 > 0.f ? t0 : SLOPE * t0; p0 += av.z * t0;
        t0 = x0.w + rv.w; t0 = t0 > 0.f ? t0 : SLOPE * t0; p0 += av.w * t0;
#pragma unroll
        for (int o = 16; o; o >>= 1) p0 += __shfl_xor_sync(0xffffffffu, p0, o);
        float mm = fmaxf(m, p0);
        float sc = __expf(m - mm);
        m = mm;
        den *= sc; acc.x *= sc; acc.y *= sc; acc.z *= sc; acc.w *= sc;
        float w0 = __expf(p0 - m);
        den += w0;
        acc.x += w0 * x0.x; acc.y += w0 * x0.y; acc.z += w0 * x0.z; acc.w += w0 * x0.w;
    }

    float inv = 1.f / den;
    float4 o4;
    float v;
    v = acc.x * inv + bias[cbase + 0]; o4.x = v > 0.f ? v : expm1f(v);
    v = acc.y * inv + bias[cbase + 1]; o4.y = v > 0.f ? v : expm1f(v);
    v = acc.z * inv + bias[cbase + 2]; o4.z = v > 0.f ? v : expm1f(v);
    v = acc.w * inv + bias[cbase + 3]; o4.w = v > 0.f ? v : expm1f(v);

    if (PERM) {
        // 4x4 transpose across the quad (lanes qb..qb+3): result r[j] = v_j[q]
        int q = lane & 3;
        int qb = lane & ~3;
        float v0 = o4.x, v1 = o4.y, v2 = o4.z, v3 = o4.w;
        // a[j] = v[(q+j)&3]
        float a0 = (q == 0) ? v0 : (q == 1) ? v1 : (q == 2) ? v2 : v3;
        float a1 = (q == 0) ? v1 : (q == 1) ? v2 : (q == 2) ? v3 : v0;
        float a2 = (q == 0) ? v2 : (q == 1) ? v3 : (q == 2) ? v0 : v1;
        float a3 = (q == 0) ? v3 : (q == 1) ? v0 : (q == 2) ? v1 : v2;
        // b[j] = shfl(a[j], qb + ((q - j) & 3))
        float b0 = a0;
        float b1 = __shfl_sync(0xffffffffu, a1, qb + ((q + 3) & 3));
        float b2 = __shfl_sync(0xffffffffu, a2, qb + ((q + 2) & 3));
        float b3 = __shfl_sync(0xffffffffu, a3, qb + ((q + 1) & 3));
        // r[j] = b[(q - j) & 3]
        float r0 = (q == 0) ? b0 : (q == 1) ? b1 : (q == 2) ? b2 : b3;
        float r1 = (q == 0) ? b3 : (q == 1) ? b0 : (q == 2) ? b1 : b2;
        float r2 = (q == 0) ? b2 : (q == 1) ? b3 : (q == 2) ? b0 : b1;
        float r3 = (q == 0) ? b1 : (q == 1) ? b2 : (q == 2) ? b3 : b0;
        float4 w4 = make_float4(f2tf32f(r0), f2tf32f(r1), f2tf32f(r2), f2tf32f(r3));
        *(float4*)(out + (size_t)node * D + cbase) = w4;
    } else {
        *(float4*)(out + (size_t)node * D + cbase) = o4;
    }
}

// ----------------------------------------------------------------------------
// Pooling (batch is sorted -> contiguous segments, no atomics) + MLP
// ----------------------------------------------------------------------------
__global__ void pool_kernel(const int* __restrict__ batch) {
    int g = blockIdx.x;
    int t = threadIdx.x;
    __shared__ int seg[2];
    if (t < 2) {
        int target = g + t;
        int lo = 0, hi = NN;
        while (lo < hi) {
            int mid = (lo + hi) >> 1;
            if (batch[mid] < target) lo = mid + 1; else hi = mid;
        }
        seg[t] = lo;
    }
    __syncthreads();
    int lo = seg[0], hi = seg[1];
    float sum = 0.f;
    for (int i = lo; i < hi; i++) sum += g_h3[(size_t)i * HID + t];
    float c = fmaxf((float)(hi - lo), 1.0f);
    g_pool[g * HID + t] = sum / c;
}
__global__ void mlp_kernel(const float* __restrict__ W1, const float* __restrict__ b1,
                           const float* __restrict__ W2, const float* __restrict__ b2,
                           float* __restrict__ out) {
    int g = blockIdx.x;
    int t = threadIdx.x;
    __shared__ float p[HID];
    __shared__ float hid[HID];
    __shared__ float red[HID];
    p[t] = g_pool[g * HID + t];
    __syncthreads();
    float a = 0.f;
    for (int k = 0; k < HID; k++) a += p[k] * W1[k * HID + t];
    hid[t] = fmaxf(a + b1[t], 0.f);
    __syncthreads();
    for (int o = 0; o < 2; o++) {
        red[t] = hid[t] * W2[t * 2 + o];
        __syncthreads();
        for (int stp = 64; stp; stp >>= 1) {
            if (t < stp) red[t] += red[t + stp];
            __syncthreads();
        }
        if (t == 0) out[g * 2 + o] = red[0] + b2[o];
        __syncthreads();
    }
}

// ----------------------------------------------------------------------------
// Launch
// ----------------------------------------------------------------------------
extern "C" void kernel_launch(void* const* d_in, const int* in_sizes, int n_in,
                              void* d_out, int out_size) {
    const float* x     = (const float*)d_in[0];
    const int*   esrc  = (const int*)d_in[1];
    const int*   edst  = (const int*)d_in[2];
    const int*   batch = (const int*)d_in[3];
    const float* Wl1 = (const float*)d_in[4];
    const float* Wr1 = (const float*)d_in[5];
    const float* bl1 = (const float*)d_in[6];
    const float* br1 = (const float*)d_in[7];
    const float* att1  = (const float*)d_in[8];
    const float* bias1 = (const float*)d_in[9];
    const float* Wl2 = (const float*)d_in[10];
    const float* Wr2 = (const float*)d_in[11];
    const float* bl2 = (const float*)d_in[12];
    const float* br2 = (const float*)d_in[13];
    const float* att2  = (const float*)d_in[14];
    const float* bias2 = (const float*)d_in[15];
    const float* Wl3 = (const float*)d_in[16];
    const float* Wr3 = (const float*)d_in[17];
    const float* bl3 = (const float*)d_in[18];
    const float* br3 = (const float*)d_in[19];
    const float* att3  = (const float*)d_in[20];
    const float* bias3 = (const float*)d_in[21];
    const float* Wm1 = (const float*)d_in[22];
    const float* bm1 = (const float*)d_in[23];
    const float* Wm2 = (const float*)d_in[24];
    const float* bm2 = (const float*)d_in[25];
    float* out = (float*)d_out;

    float *p_xlr, *p_h1, *p_h2, *p_h3, *p_xp, *p_wt;
    cudaGetSymbolAddress((void**)&p_xlr, g_xlr);
    cudaGetSymbolAddress((void**)&p_h1, g_h1);
    cudaGetSymbolAddress((void**)&p_h2, g_h2);
    cudaGetSymbolAddress((void**)&p_h3, g_h3);
    cudaGetSymbolAddress((void**)&p_xp, g_xp);
    cudaGetSymbolAddress((void**)&p_wt, g_wt);

    const int SMEM = 2 * (SMEM_A_TILE + SMEM_B_TILE) * 4;  // 65536 bytes
    cudaFuncSetAttribute(gemm_mma, cudaFuncAttributeMaxDynamicSharedMemorySize, SMEM);

    const int RT = (NN + 127) / 128;  // 157 row tiles
    dim3 tb(32, 8);

    // --- front: layer-1 GEMM path first (gemm_mma at stream position 4 for ncu) ---
    permute_x_kernel<<<(NN * FIN + 255) / 256, 256>>>(x, p_xp);                 // 1
    transpose_kernel<<<dim3(16, 4), tb>>>(Wl1, p_wt, 128, 512);                 // 2
    transpose_kernel<<<dim3(16, 4), tb>>>(Wr1, p_wt + 512 * 128, 128, 512);     // 3
    gemm_mma<<<dim3(RT, 8), 256, SMEM>>>(p_xp, p_wt, bl1, br1, p_xlr,           // 4
                                         NN, 128, 1024, 512);

    // --- CSR build (only needed before attention) ---
    zero_kernel<<<(NN + 255) / 256, 256>>>();
    hist_kernel<<<(ET + 255) / 256, 256>>>(edst);
    scan_kernel<<<1, 1024>>>();
    scatter_kernel<<<(ET + 255) / 256, 256>>>(esrc, edst);

    gatv2_fused<HEADS, true><<<(NN * HEADS + 7) / 8, 256>>>(p_xlr, att1, bias1, p_h1);

    // Layer 2
    transpose_kernel<<<dim3(16, 16), tb>>>(Wl2, p_wt, 512, 512);
    transpose_kernel<<<dim3(16, 16), tb>>>(Wr2, p_wt + 512 * 512, 512, 512);
    gemm_mma<<<dim3(RT, 8), 256, SMEM>>>(p_h1, p_wt, bl2, br2, p_xlr, NN, 512, 1024, 512);
    gatv2_fused<HEADS, true><<<(NN * HEADS + 7) / 8, 256>>>(p_xlr, att2, bias2, p_h2);

    // Layer 3
    transpose_kernel<<<dim3(4, 16), tb>>>(Wl3, p_wt, 512, 128);
    transpose_kernel<<<dim3(4, 16), tb>>>(Wr3, p_wt + 128 * 512, 512, 128);
    gemm_mma<<<dim3(RT, 2), 256, SMEM>>>(p_h2, p_wt, bl3, br3, p_xlr, NN, 512, 256, 128);
    gatv2_fused<1, false><<<(NN + 7) / 8, 256>>>(p_xlr, att3, bias3, p_h3);

    // Pool + MLP
    pool_kernel<<<BGR, HID>>>(batch);
    mlp_kernel<<<BGR, HID>>>(Wm1, bm1, Wm2, bm2, out);
}